// round 7
// baseline (speedup 1.0000x reference)
#include <cuda_runtime.h>

#define NN 200000
#define EE 3200000
#define HH 16
#define CC 4
#define GG 256
#define NB ((NN + 1023) / 1024)   // scan blocks = 196

// Scratch (allocation-free __device__ globals); 16B alignment for float4 paths.
__device__ int   g_cnt[NN];            // in-degree histogram
__device__ int   g_rowptr[NN + 1];     // CSR row pointers (by dst)
__device__ int   g_cur[NN];            // fill cursors
__device__ int   g_bsum[NB];           // scan block sums
__device__ float g_dinv[NN];           // rsqrt(deg+1)
__device__ int   g_csr_src[EE];        // src node per CSR slot
__device__ __align__(16) float g_csr_norm[EE];  // per-edge symmetric norm
__device__ __align__(16) float g_bufA[NN * HH]; // layer output ping
__device__ __align__(16) float g_bufB[NN * HH]; // layer output pong

__global__ void zero_kernel() {
    int n = blockIdx.x * blockDim.x + threadIdx.x;
    if (n < NN) g_cnt[n] = 0;
}

// histogram of dst (edge_index arrives as int32: harness converts int64->int32)
__global__ void hist_kernel(const int* __restrict__ ei) {
    int e = blockIdx.x * blockDim.x + threadIdx.x;
    if (e < EE) atomicAdd(&g_cnt[ei[EE + e]], 1);
}

// ---- scan of g_cnt -> g_rowptr (3 kernels); scan1 also computes dinv ----
__device__ __forceinline__ int block_inclusive_scan(int v) {
    __shared__ int ws[32];
    int lane = threadIdx.x & 31, wid = threadIdx.x >> 5;
    int x = v;
#pragma unroll
    for (int o = 1; o < 32; o <<= 1) {
        int y = __shfl_up_sync(0xffffffffu, x, o);
        if (lane >= o) x += y;
    }
    if (lane == 31) ws[wid] = x;
    __syncthreads();
    if (wid == 0) {
        int nw = blockDim.x >> 5;
        int w = (lane < nw) ? ws[lane] : 0;
#pragma unroll
        for (int o = 1; o < 32; o <<= 1) {
            int y = __shfl_up_sync(0xffffffffu, w, o);
            if (lane >= o) w += y;
        }
        ws[lane] = w;
    }
    __syncthreads();
    int base = (wid > 0) ? ws[wid - 1] : 0;
    return x + base;   // inclusive across block
}

__global__ void scan1_kernel() {   // per-block exclusive scan + block totals + dinv
    int i = blockIdx.x * 1024 + threadIdx.x;
    int v = (i < NN) ? g_cnt[i] : 0;
    if (i < NN) g_dinv[i] = rsqrtf((float)v + 1.0f);
    int incl = block_inclusive_scan(v);
    if (i < NN) g_rowptr[i] = incl - v;
    if (threadIdx.x == 1023) g_bsum[blockIdx.x] = incl;
}

__global__ void scan2_kernel() {   // exclusive scan of block totals (single block)
    int i = threadIdx.x;
    int v = (i < NB) ? g_bsum[i] : 0;
    int incl = block_inclusive_scan(v);
    if (i < NB) g_bsum[i] = incl - v;
}

__global__ void scan3_kernel() {   // add block offsets; init cursors; cap rowptr
    int i = blockIdx.x * blockDim.x + threadIdx.x;
    if (i < NN) {
        int val = g_rowptr[i] + g_bsum[i >> 10];
        g_rowptr[i] = val;
        g_cur[i] = val;
    }
    if (i == 0) g_rowptr[NN] = EE;
}

// fill CSR slots: src id + precomputed symmetric norm
__global__ void fill_kernel(const int* __restrict__ ei) {
    int e = blockIdx.x * blockDim.x + threadIdx.x;
    if (e >= EE) return;
    int s = ei[e];
    int d = ei[EE + e];
    int pos = atomicAdd(&g_cur[d], 1);
    g_csr_src[pos] = s;
    g_csr_norm[pos] = g_dinv[s] * g_dinv[d];
}

// Fused GCN layer (pull mode + transform epilogue), one warp per node:
//   z = A_norm @ in   (gather+reduce, incl. self-loop)
//   out = [relu](z @ W + b)
// Lanes: 8 edge-slots x 4 column-chunks for the gather; 16 lanes for epilogue.
template <bool RELU>
__global__ void agg_kernel(const float* __restrict__ in,
                           const float* __restrict__ W,
                           const float* __restrict__ b,
                           float* __restrict__ outbuf) {
    __shared__ float Ws[HH * HH];
    __shared__ float Bs[HH];
    __shared__ float Z[8][HH];          // one row per warp (256 threads = 8 warps)
    int tid = threadIdx.x;
    if (tid < HH * HH) Ws[tid] = W[tid];
    if (tid < HH) Bs[tid] = b[tid];
    __syncthreads();

    int gw = (blockIdx.x * blockDim.x + tid) >> 5;   // node id (whole warp shares it)
    if (gw >= NN) return;
    int lane = tid & 31;
    int warp = tid >> 5;
    int beg = g_rowptr[gw], end = g_rowptr[gw + 1];
    int c = lane & 3;      // 16B column chunk
    int eo = lane >> 2;    // edge slot 0..7

    float4 a = make_float4(0.0f, 0.0f, 0.0f, 0.0f);
    for (int i = beg + eo; i < end; i += 8) {
        int s = g_csr_src[i];
        float w = g_csr_norm[i];
        float4 v = __ldg((const float4*)(in + (size_t)s * HH) + c);
        a.x += v.x * w; a.y += v.y * w; a.z += v.z * w; a.w += v.w * w;
    }
#pragma unroll
    for (int o = 16; o >= 4; o >>= 1) {
        a.x += __shfl_down_sync(0xffffffffu, a.x, o);
        a.y += __shfl_down_sync(0xffffffffu, a.y, o);
        a.z += __shfl_down_sync(0xffffffffu, a.z, o);
        a.w += __shfl_down_sync(0xffffffffu, a.w, o);
    }
    if (lane < 4) {
        float di = g_dinv[gw];
        float w = di * di;                          // self-loop norm
        float4 v = __ldg((const float4*)(in + (size_t)gw * HH) + lane);
        a.x += v.x * w; a.y += v.y * w; a.z += v.z * w; a.w += v.w * w;
        Z[warp][lane * 4 + 0] = a.x;
        Z[warp][lane * 4 + 1] = a.y;
        Z[warp][lane * 4 + 2] = a.z;
        Z[warp][lane * 4 + 3] = a.w;
    }
    __syncwarp();
    if (lane < HH) {
        float acc = Bs[lane];
#pragma unroll
        for (int k = 0; k < HH; k++) acc += Z[warp][k] * Ws[k * HH + lane];
        if (RELU) acc = fmaxf(acc, 0.0f);
        outbuf[(size_t)gw * HH + lane] = acc;
    }
}

// One block per graph: binary-search sorted batch, block-reduce, head + log_softmax.
__global__ void pool_head_kernel(const int* __restrict__ batch,
                                 const float* __restrict__ Wlin,
                                 const float* __restrict__ blin,
                                 const float* __restrict__ feat,
                                 float* __restrict__ out) {
    int g = blockIdx.x;
    int tid = threadIdx.x;

    int lo = 0, hi = NN;
    while (lo < hi) { int m = (lo + hi) >> 1; if (batch[m] < g) lo = m + 1; else hi = m; }
    int beg = lo;
    lo = beg; hi = NN;
    int g1 = g + 1;
    while (lo < hi) { int m = (lo + hi) >> 1; if (batch[m] < g1) lo = m + 1; else hi = m; }
    int end = lo;

    float s[HH];
#pragma unroll
    for (int f = 0; f < HH; f++) s[f] = 0.0f;

    for (int n = beg + tid; n < end; n += blockDim.x) {
        const float4* p = (const float4*)(feat + (size_t)n * HH);
#pragma unroll
        for (int q = 0; q < 4; q++) {
            float4 v = p[q];
            s[q * 4 + 0] += v.x; s[q * 4 + 1] += v.y;
            s[q * 4 + 2] += v.z; s[q * 4 + 3] += v.w;
        }
    }
#pragma unroll
    for (int off = 16; off > 0; off >>= 1) {
#pragma unroll
        for (int f = 0; f < HH; f++)
            s[f] += __shfl_down_sync(0xffffffffu, s[f], off);
    }

    __shared__ float red[8][HH];
    int warp = tid >> 5, lane = tid & 31;
    if (lane == 0) {
#pragma unroll
        for (int f = 0; f < HH; f++) red[warp][f] = s[f];
    }
    __syncthreads();

    if (tid == 0) {
        float tot[HH];
        int nwarps = blockDim.x >> 5;
#pragma unroll
        for (int f = 0; f < HH; f++) {
            float t = 0.0f;
            for (int w = 0; w < nwarps; w++) t += red[w][f];
            tot[f] = t;
        }
        float cnt = (float)(end - beg);
        float inv = 1.0f / fmaxf(cnt, 1.0f);
        float pooled[HH];
#pragma unroll
        for (int f = 0; f < HH; f++) pooled[f] = tot[f] * inv;

        float logit[CC];
#pragma unroll
        for (int c = 0; c < CC; c++) {
            float a = blin[c];
#pragma unroll
            for (int f = 0; f < HH; f++) a += pooled[f] * Wlin[f * CC + c];
            logit[c] = a;
        }
        float m = logit[0];
#pragma unroll
        for (int c = 1; c < CC; c++) m = fmaxf(m, logit[c]);
        float se = 0.0f;
#pragma unroll
        for (int c = 0; c < CC; c++) se += expf(logit[c] - m);
        float lse = m + logf(se);
#pragma unroll
        for (int c = 0; c < CC; c++) out[g * CC + c] = logit[c] - lse;
    }
}

extern "C" void kernel_launch(void* const* d_in, const int* in_sizes, int n_in,
                              void* d_out, int out_size) {
    // Bind inputs by element count (robust to metadata ordering).
    const float *x = 0, *W1 = 0, *b1 = 0, *W2 = 0, *b2 = 0, *W3 = 0, *b3 = 0;
    const float *Wlin = 0, *blin = 0;
    const int *ei = 0, *batch = 0;
    int wseen = 0, bseen = 0;
    for (int i = 0; i < n_in; i++) {
        int s = in_sizes[i];
        const void* p = d_in[i];
        if (s == NN * HH)        x = (const float*)p;
        else if (s == 2 * EE)    ei = (const int*)p;
        else if (s == NN)        batch = (const int*)p;
        else if (s == HH * HH) {
            if (wseen == 0) W1 = (const float*)p;
            else if (wseen == 1) W2 = (const float*)p;
            else W3 = (const float*)p;
            wseen++;
        } else if (s == HH) {
            if (bseen == 0) b1 = (const float*)p;
            else if (bseen == 1) b2 = (const float*)p;
            else b3 = (const float*)p;
            bseen++;
        } else if (s == HH * CC) Wlin = (const float*)p;
        else if (s == CC)        blin = (const float*)p;
    }
    float* out = (float*)d_out;

    const int B = 256;
    const int gN = (NN + B - 1) / B;
    const int gE = (EE + B - 1) / B;
    const int gW = (NN * 32 + B - 1) / B;   // warp-per-node

    static float* bufA = nullptr;
    static float* bufB = nullptr;
    if (!bufA) {
        cudaGetSymbolAddress((void**)&bufA, g_bufA);
        cudaGetSymbolAddress((void**)&bufB, g_bufB);
    }

    // CSR build
    zero_kernel<<<gN, B>>>();
    hist_kernel<<<gE, B>>>(ei);
    scan1_kernel<<<NB, 1024>>>();
    scan2_kernel<<<1, 1024>>>();
    scan3_kernel<<<gN, B>>>();
    fill_kernel<<<gE, B>>>(ei);

    // 3 fused GCN layers: out = [relu]((A_norm @ in) @ W + b)
    agg_kernel<true ><<<gW, B>>>(x,    W1, b1, bufA);
    agg_kernel<true ><<<gW, B>>>(bufA, W2, b2, bufB);
    agg_kernel<false><<<gW, B>>>(bufB, W3, b3, bufA);

    pool_head_kernel<<<GG, B>>>(batch, Wlin, blin, bufA, out);
}

// round 8
// speedup vs baseline: 1.1449x; 1.1449x over previous
#include <cuda_runtime.h>
#include <cuda_fp16.h>

#define NN 200000
#define EE 3200000
#define HH 16
#define CC 4
#define GG 256

// Scratch (allocation-free __device__ globals). 16B alignment for vector paths.
__device__ int    g_cnt[NN];                       // in-degree histogram (int)
__device__ float  g_dinv[NN];                      // rsqrt(deg+1)
__device__ __align__(16) int2   g_sd[EE];          // packed (src,dst)
__device__ __align__(16) float  g_norm[EE];        // per-edge symmetric norm (filled by scatter1)
__device__ __align__(16) __half g_t[NN * HH];      // transformed features, f16 (gather source)
__device__ __align__(16) float  g_acc[NN * HH];    // scatter accumulator / layer output (f32)

__global__ void zero_kernel() {
    int n = blockIdx.x * blockDim.x + threadIdx.x;
    if (n < NN) g_cnt[n] = 0;
}

// Read edge_index (int32 from harness) once: pack (src,dst), histogram dst.
__global__ void deg_kernel(const int* __restrict__ ei) {
    int e = blockIdx.x * blockDim.x + threadIdx.x;
    if (e >= EE) return;
    int s = ei[e];
    int d = ei[EE + e];
    g_sd[e] = make_int2(s, d);
    atomicAdd(&g_cnt[d], 1);
}

__global__ void dinv_kernel() {
    int n = blockIdx.x * blockDim.x + threadIdx.x;
    if (n < NN) g_dinv[n] = rsqrtf((float)g_cnt[n] + 1.0f);
}

// Fused: (optional bias+ReLU of previous layer) -> h @ W.
// Writes g_t (f16, gather source) and seeds g_acc with self-loop term t*dinv^2 (f32).
template <bool FIRST>
__global__ void transform_kernel(const float* __restrict__ in,
                                 const float* __restrict__ W,
                                 const float* __restrict__ bprev) {
    __shared__ float Ws[HH * HH];
    __shared__ float Bs[HH];
    int tid = threadIdx.x;
    if (tid < HH * HH) Ws[tid] = W[tid];
    if (!FIRST && tid < HH) Bs[tid] = bprev[tid];
    __syncthreads();

    int n = blockIdx.x * blockDim.x + tid;
    if (n >= NN) return;

    float h[HH];
    if (FIRST) {
        const float4* p = (const float4*)(in + (size_t)n * HH);
#pragma unroll
        for (int q = 0; q < 4; q++) {
            float4 v = p[q];
            h[q * 4 + 0] = v.x; h[q * 4 + 1] = v.y;
            h[q * 4 + 2] = v.z; h[q * 4 + 3] = v.w;
        }
    } else {
        const float4* p = (const float4*)(g_acc + (size_t)n * HH);
#pragma unroll
        for (int q = 0; q < 4; q++) {
            float4 v = p[q];
            h[q * 4 + 0] = fmaxf(v.x + Bs[q * 4 + 0], 0.0f);
            h[q * 4 + 1] = fmaxf(v.y + Bs[q * 4 + 1], 0.0f);
            h[q * 4 + 2] = fmaxf(v.z + Bs[q * 4 + 2], 0.0f);
            h[q * 4 + 3] = fmaxf(v.w + Bs[q * 4 + 3], 0.0f);
        }
    }

    float o[HH];
#pragma unroll
    for (int j = 0; j < HH; j++) o[j] = 0.0f;
#pragma unroll
    for (int k = 0; k < HH; k++) {
#pragma unroll
        for (int j = 0; j < HH; j += 4) {
            float4 w = *(const float4*)&Ws[k * HH + j];
            o[j + 0] += h[k] * w.x;
            o[j + 1] += h[k] * w.y;
            o[j + 2] += h[k] * w.z;
            o[j + 3] += h[k] * w.w;
        }
    }

    float di = g_dinv[n];
    float d2 = di * di;                              // self-loop norm
    // f16 gather row: 16 halves = 32B = 4x uint2
    uint2* tp = (uint2*)(g_t + (size_t)n * HH);
    float4* ap = (float4*)(g_acc + (size_t)n * HH);
#pragma unroll
    for (int q = 0; q < 4; q++) {
        __half2 lo = __floats2half2_rn(o[q * 4 + 0], o[q * 4 + 1]);
        __half2 hi = __floats2half2_rn(o[q * 4 + 2], o[q * 4 + 3]);
        uint2 pk;
        pk.x = *(unsigned int*)&lo;
        pk.y = *(unsigned int*)&hi;
        tp[q] = pk;
        ap[q] = make_float4(o[q * 4 + 0] * d2, o[q * 4 + 1] * d2,
                            o[q * 4 + 2] * d2, o[q * 4 + 3] * d2);
    }
}

// Edge scatter: acc[dst] += t[src] * norm. 4 threads/edge, thread c handles cols
// 4c..4c+3: one 8B f16 gather + one red.global.add.v4.f32.
// COMPUTE_NORM (layer 1): norm computed from dinv on the fly, lane c==0 stores it.
template <bool COMPUTE_NORM>
__global__ void scatter_kernel() {
    int gid = blockIdx.x * blockDim.x + threadIdx.x;
    if (gid >= EE * 4) return;
    int e = gid >> 2;
    int c = gid & 3;
    int2 sd = g_sd[e];
    float w;
    if (COMPUTE_NORM) {
        w = g_dinv[sd.x] * g_dinv[sd.y];
        if (c == 0) g_norm[e] = w;
    } else {
        w = g_norm[e];
    }
    uint2 pk = __ldg((const uint2*)(g_t + (size_t)sd.x * HH) + c);
    __half2 lo = *(__half2*)&pk.x;
    __half2 hi = *(__half2*)&pk.y;
    float2 f0 = __half22float2(lo);
    float2 f1 = __half22float2(hi);
    float* a = g_acc + (size_t)sd.y * HH + c * 4;
    asm volatile("red.global.add.v4.f32 [%0], {%1, %2, %3, %4};"
                 :: "l"(a), "f"(f0.x * w), "f"(f0.y * w), "f"(f1.x * w), "f"(f1.y * w)
                 : "memory");
}

// One block per graph: binary-search sorted batch, block-reduce, head + log_softmax.
__global__ void pool_head_kernel(const int* __restrict__ batch,
                                 const float* __restrict__ b3,
                                 const float* __restrict__ Wlin,
                                 const float* __restrict__ blin,
                                 float* __restrict__ out) {
    int g = blockIdx.x;
    int tid = threadIdx.x;

    int lo = 0, hi = NN;
    while (lo < hi) { int m = (lo + hi) >> 1; if (batch[m] < g) lo = m + 1; else hi = m; }
    int beg = lo;
    lo = beg; hi = NN;
    int g1 = g + 1;
    while (lo < hi) { int m = (lo + hi) >> 1; if (batch[m] < g1) lo = m + 1; else hi = m; }
    int end = lo;

    float s[HH];
#pragma unroll
    for (int f = 0; f < HH; f++) s[f] = 0.0f;

    for (int n = beg + tid; n < end; n += blockDim.x) {
        const float4* p = (const float4*)(g_acc + (size_t)n * HH);
#pragma unroll
        for (int q = 0; q < 4; q++) {
            float4 v = p[q];
            s[q * 4 + 0] += v.x; s[q * 4 + 1] += v.y;
            s[q * 4 + 2] += v.z; s[q * 4 + 3] += v.w;
        }
    }
#pragma unroll
    for (int off = 16; off > 0; off >>= 1) {
#pragma unroll
        for (int f = 0; f < HH; f++)
            s[f] += __shfl_down_sync(0xffffffffu, s[f], off);
    }

    __shared__ float red[8][HH];
    int warp = tid >> 5, lane = tid & 31;
    if (lane == 0) {
#pragma unroll
        for (int f = 0; f < HH; f++) red[warp][f] = s[f];
    }
    __syncthreads();

    if (tid == 0) {
        float tot[HH];
        int nwarps = blockDim.x >> 5;
#pragma unroll
        for (int f = 0; f < HH; f++) {
            float t = 0.0f;
            for (int w = 0; w < nwarps; w++) t += red[w][f];
            tot[f] = t;
        }
        float cnt = (float)(end - beg);
        float inv = 1.0f / fmaxf(cnt, 1.0f);
        float pooled[HH];
#pragma unroll
        for (int f = 0; f < HH; f++) pooled[f] = (tot[f] + cnt * b3[f]) * inv;

        float logit[CC];
#pragma unroll
        for (int c = 0; c < CC; c++) {
            float a = blin[c];
#pragma unroll
            for (int f = 0; f < HH; f++) a += pooled[f] * Wlin[f * CC + c];
            logit[c] = a;
        }
        float m = logit[0];
#pragma unroll
        for (int c = 1; c < CC; c++) m = fmaxf(m, logit[c]);
        float se = 0.0f;
#pragma unroll
        for (int c = 0; c < CC; c++) se += expf(logit[c] - m);
        float lse = m + logf(se);
#pragma unroll
        for (int c = 0; c < CC; c++) out[g * CC + c] = logit[c] - lse;
    }
}

extern "C" void kernel_launch(void* const* d_in, const int* in_sizes, int n_in,
                              void* d_out, int out_size) {
    // Bind inputs by element count (robust to metadata ordering).
    const float *x = 0, *W1 = 0, *b1 = 0, *W2 = 0, *b2 = 0, *W3 = 0, *b3 = 0;
    const float *Wlin = 0, *blin = 0;
    const int *ei = 0, *batch = 0;
    int wseen = 0, bseen = 0;
    for (int i = 0; i < n_in; i++) {
        int s = in_sizes[i];
        const void* p = d_in[i];
        if (s == NN * HH)        x = (const float*)p;
        else if (s == 2 * EE)    ei = (const int*)p;
        else if (s == NN)        batch = (const int*)p;
        else if (s == HH * HH) {
            if (wseen == 0) W1 = (const float*)p;
            else if (wseen == 1) W2 = (const float*)p;
            else W3 = (const float*)p;
            wseen++;
        } else if (s == HH) {
            if (bseen == 0) b1 = (const float*)p;
            else if (bseen == 1) b2 = (const float*)p;
            else b3 = (const float*)p;
            bseen++;
        } else if (s == HH * CC) Wlin = (const float*)p;
        else if (s == CC)        blin = (const float*)p;
    }
    float* out = (float*)d_out;

    const int B = 256;
    const int gN = (NN + B - 1) / B;
    const int gE = (EE + B - 1) / B;
    const int gE4 = (EE * 4 + B - 1) / B;

    zero_kernel<<<gN, B>>>();
    deg_kernel<<<gE, B>>>(ei);
    dinv_kernel<<<gN, B>>>();

    transform_kernel<true><<<gN, B>>>(x, W1, nullptr);
    scatter_kernel<true><<<gE4, B>>>();              // computes + stores norm
    transform_kernel<false><<<gN, B>>>(nullptr, W2, b1);
    scatter_kernel<false><<<gE4, B>>>();
    transform_kernel<false><<<gN, B>>>(nullptr, W3, b2);
    scatter_kernel<false><<<gE4, B>>>();

    pool_head_kernel<<<GG, B>>>(batch, b3, Wlin, blin, out);
}

// round 9
// speedup vs baseline: 1.4198x; 1.2402x over previous
#include <cuda_runtime.h>
#include <cuda_fp16.h>

#define NN 200000
#define EE 3200000
#define HH 16
#define CC 4
#define GG 256

// Scratch (allocation-free __device__ globals). 16B alignment for vector paths.
__device__ int    g_cnt[NN];                       // in-degree histogram
__device__ float  g_dinv[NN];                      // rsqrt(deg+1)
__device__ __align__(16) int2   g_sd[EE];          // packed (src,dst)
__device__ __align__(16) float  g_norm[EE];        // per-edge norm (filled by scatter1)
__device__ __align__(16) __half g_t[NN * HH];      // transformed features, f16 (gather src)
__device__ __align__(16) __half g_acc[NN * HH];    // f16 accumulator (v4.f16x2 RED target)

__device__ __forceinline__ unsigned int pack2(float a, float b) {
    __half2 h = __floats2half2_rn(a, b);
    return *(unsigned int*)&h;
}
__device__ __forceinline__ float2 unpack2(unsigned int u) {
    return __half22float2(*(__half2*)&u);
}

__global__ void zero_kernel() {
    int n = blockIdx.x * blockDim.x + threadIdx.x;
    if (n < NN) g_cnt[n] = 0;
}

// Read edge_index (int32 from harness) once: pack (src,dst), histogram dst.
__global__ void deg_kernel(const int* __restrict__ ei) {
    int e = blockIdx.x * blockDim.x + threadIdx.x;
    if (e >= EE) return;
    int s = ei[e];
    int d = ei[EE + e];
    g_sd[e] = make_int2(s, d);
    atomicAdd(&g_cnt[d], 1);
}

__global__ void dinv_kernel() {
    int n = blockIdx.x * blockDim.x + threadIdx.x;
    if (n < NN) g_dinv[n] = rsqrtf((float)g_cnt[n] + 1.0f);
}

// Fused: (optional bias+ReLU of previous f16 accumulator) -> h @ W  (f32 math).
// Writes g_t (f16) and seeds g_acc (f16) with the self-loop term t*dinv^2.
template <bool FIRST>
__global__ void transform_kernel(const float* __restrict__ in,
                                 const float* __restrict__ W,
                                 const float* __restrict__ bprev) {
    __shared__ float Ws[HH * HH];
    __shared__ float Bs[HH];
    int tid = threadIdx.x;
    if (tid < HH * HH) Ws[tid] = W[tid];
    if (!FIRST && tid < HH) Bs[tid] = bprev[tid];
    __syncthreads();

    int n = blockIdx.x * blockDim.x + tid;
    if (n >= NN) return;

    float h[HH];
    if (FIRST) {
        const float4* p = (const float4*)(in + (size_t)n * HH);
#pragma unroll
        for (int q = 0; q < 4; q++) {
            float4 v = p[q];
            h[q * 4 + 0] = v.x; h[q * 4 + 1] = v.y;
            h[q * 4 + 2] = v.z; h[q * 4 + 3] = v.w;
        }
    } else {
        const uint4* p = (const uint4*)(g_acc + (size_t)n * HH);
#pragma unroll
        for (int q = 0; q < 2; q++) {
            uint4 pk = p[q];
            float2 f0 = unpack2(pk.x), f1 = unpack2(pk.y);
            float2 f2 = unpack2(pk.z), f3 = unpack2(pk.w);
            int b = q * 8;
            h[b + 0] = fmaxf(f0.x + Bs[b + 0], 0.0f);
            h[b + 1] = fmaxf(f0.y + Bs[b + 1], 0.0f);
            h[b + 2] = fmaxf(f1.x + Bs[b + 2], 0.0f);
            h[b + 3] = fmaxf(f1.y + Bs[b + 3], 0.0f);
            h[b + 4] = fmaxf(f2.x + Bs[b + 4], 0.0f);
            h[b + 5] = fmaxf(f2.y + Bs[b + 5], 0.0f);
            h[b + 6] = fmaxf(f3.x + Bs[b + 6], 0.0f);
            h[b + 7] = fmaxf(f3.y + Bs[b + 7], 0.0f);
        }
    }

    float o[HH];
#pragma unroll
    for (int j = 0; j < HH; j++) o[j] = 0.0f;
#pragma unroll
    for (int k = 0; k < HH; k++) {
#pragma unroll
        for (int j = 0; j < HH; j += 4) {
            float4 w = *(const float4*)&Ws[k * HH + j];
            o[j + 0] += h[k] * w.x;
            o[j + 1] += h[k] * w.y;
            o[j + 2] += h[k] * w.z;
            o[j + 3] += h[k] * w.w;
        }
    }

    float di = g_dinv[n];
    float d2 = di * di;                              // self-loop norm
    uint4* tp = (uint4*)(g_t + (size_t)n * HH);
    uint4* ap = (uint4*)(g_acc + (size_t)n * HH);
#pragma unroll
    for (int q = 0; q < 2; q++) {
        int b = q * 8;
        uint4 t;
        t.x = pack2(o[b + 0], o[b + 1]);
        t.y = pack2(o[b + 2], o[b + 3]);
        t.z = pack2(o[b + 4], o[b + 5]);
        t.w = pack2(o[b + 6], o[b + 7]);
        tp[q] = t;
        uint4 a;
        a.x = pack2(o[b + 0] * d2, o[b + 1] * d2);
        a.y = pack2(o[b + 2] * d2, o[b + 3] * d2);
        a.z = pack2(o[b + 4] * d2, o[b + 5] * d2);
        a.w = pack2(o[b + 6] * d2, o[b + 7] * d2);
        ap[q] = a;
    }
}

// Edge scatter: acc[dst] += t[src] * norm. 2 threads/edge, thread c handles 8
// halves (16B): one 16B f16 gather + ONE red.global.add.noftz.v4.f16x2.
// COMPUTE_NORM (layer 1): norm computed from dinv on the fly, c==0 stores it.
template <bool COMPUTE_NORM>
__global__ void scatter_kernel() {
    int gid = blockIdx.x * blockDim.x + threadIdx.x;
    if (gid >= EE * 2) return;
    int e = gid >> 1;
    int c = gid & 1;
    int2 sd = g_sd[e];
    float w;
    if (COMPUTE_NORM) {
        w = g_dinv[sd.x] * g_dinv[sd.y];
        if (c == 0) g_norm[e] = w;
    } else {
        w = g_norm[e];
    }
    uint4 pk = __ldg((const uint4*)(g_t + (size_t)sd.x * HH) + c);
    float2 f0 = unpack2(pk.x), f1 = unpack2(pk.y);
    float2 f2 = unpack2(pk.z), f3 = unpack2(pk.w);
    unsigned int r0 = pack2(f0.x * w, f0.y * w);
    unsigned int r1 = pack2(f1.x * w, f1.y * w);
    unsigned int r2 = pack2(f2.x * w, f2.y * w);
    unsigned int r3 = pack2(f3.x * w, f3.y * w);
    __half* a = g_acc + (size_t)sd.y * HH + c * 8;
    asm volatile("red.global.add.noftz.v4.f16x2 [%0], {%1, %2, %3, %4};"
                 :: "l"(a), "r"(r0), "r"(r1), "r"(r2), "r"(r3)
                 : "memory");
}

// One block per graph: binary-search sorted batch, block-reduce (f32),
// head + log_softmax.
__global__ void pool_head_kernel(const int* __restrict__ batch,
                                 const float* __restrict__ b3,
                                 const float* __restrict__ Wlin,
                                 const float* __restrict__ blin,
                                 float* __restrict__ out) {
    int g = blockIdx.x;
    int tid = threadIdx.x;

    int lo = 0, hi = NN;
    while (lo < hi) { int m = (lo + hi) >> 1; if (batch[m] < g) lo = m + 1; else hi = m; }
    int beg = lo;
    lo = beg; hi = NN;
    int g1 = g + 1;
    while (lo < hi) { int m = (lo + hi) >> 1; if (batch[m] < g1) lo = m + 1; else hi = m; }
    int end = lo;

    float s[HH];
#pragma unroll
    for (int f = 0; f < HH; f++) s[f] = 0.0f;

    for (int n = beg + tid; n < end; n += blockDim.x) {
        const uint4* p = (const uint4*)(g_acc + (size_t)n * HH);
#pragma unroll
        for (int q = 0; q < 2; q++) {
            uint4 pk = p[q];
            float2 f0 = unpack2(pk.x), f1 = unpack2(pk.y);
            float2 f2 = unpack2(pk.z), f3 = unpack2(pk.w);
            int b = q * 8;
            s[b + 0] += f0.x; s[b + 1] += f0.y;
            s[b + 2] += f1.x; s[b + 3] += f1.y;
            s[b + 4] += f2.x; s[b + 5] += f2.y;
            s[b + 6] += f3.x; s[b + 7] += f3.y;
        }
    }
#pragma unroll
    for (int off = 16; off > 0; off >>= 1) {
#pragma unroll
        for (int f = 0; f < HH; f++)
            s[f] += __shfl_down_sync(0xffffffffu, s[f], off);
    }

    __shared__ float red[8][HH];
    int warp = tid >> 5, lane = tid & 31;
    if (lane == 0) {
#pragma unroll
        for (int f = 0; f < HH; f++) red[warp][f] = s[f];
    }
    __syncthreads();

    if (tid == 0) {
        float tot[HH];
        int nwarps = blockDim.x >> 5;
#pragma unroll
        for (int f = 0; f < HH; f++) {
            float t = 0.0f;
            for (int w = 0; w < nwarps; w++) t += red[w][f];
            tot[f] = t;
        }
        float cnt = (float)(end - beg);
        float inv = 1.0f / fmaxf(cnt, 1.0f);
        float pooled[HH];
#pragma unroll
        for (int f = 0; f < HH; f++) pooled[f] = (tot[f] + cnt * b3[f]) * inv;

        float logit[CC];
#pragma unroll
        for (int c = 0; c < CC; c++) {
            float a = blin[c];
#pragma unroll
            for (int f = 0; f < HH; f++) a += pooled[f] * Wlin[f * CC + c];
            logit[c] = a;
        }
        float m = logit[0];
#pragma unroll
        for (int c = 1; c < CC; c++) m = fmaxf(m, logit[c]);
        float se = 0.0f;
#pragma unroll
        for (int c = 0; c < CC; c++) se += expf(logit[c] - m);
        float lse = m + logf(se);
#pragma unroll
        for (int c = 0; c < CC; c++) out[g * CC + c] = logit[c] - lse;
    }
}

extern "C" void kernel_launch(void* const* d_in, const int* in_sizes, int n_in,
                              void* d_out, int out_size) {
    // Bind inputs by element count (robust to metadata ordering).
    const float *x = 0, *W1 = 0, *b1 = 0, *W2 = 0, *b2 = 0, *W3 = 0, *b3 = 0;
    const float *Wlin = 0, *blin = 0;
    const int *ei = 0, *batch = 0;
    int wseen = 0, bseen = 0;
    for (int i = 0; i < n_in; i++) {
        int s = in_sizes[i];
        const void* p = d_in[i];
        if (s == NN * HH)        x = (const float*)p;
        else if (s == 2 * EE)    ei = (const int*)p;
        else if (s == NN)        batch = (const int*)p;
        else if (s == HH * HH) {
            if (wseen == 0) W1 = (const float*)p;
            else if (wseen == 1) W2 = (const float*)p;
            else W3 = (const float*)p;
            wseen++;
        } else if (s == HH) {
            if (bseen == 0) b1 = (const float*)p;
            else if (bseen == 1) b2 = (const float*)p;
            else b3 = (const float*)p;
            bseen++;
        } else if (s == HH * CC) Wlin = (const float*)p;
        else if (s == CC)        blin = (const float*)p;
    }
    float* out = (float*)d_out;

    const int B = 256;
    const int gN = (NN + B - 1) / B;
    const int gE = (EE + B - 1) / B;
    const int gE2 = (EE * 2 + B - 1) / B;

    zero_kernel<<<gN, B>>>();
    deg_kernel<<<gE, B>>>(ei);
    dinv_kernel<<<gN, B>>>();

    transform_kernel<true><<<gN, B>>>(x, W1, nullptr);
    scatter_kernel<true><<<gE2, B>>>();              // computes + stores norm
    transform_kernel<false><<<gN, B>>>(nullptr, W2, b1);
    scatter_kernel<false><<<gE2, B>>>();
    transform_kernel<false><<<gN, B>>>(nullptr, W3, b2);
    scatter_kernel<false><<<gE2, B>>>();

    pool_head_kernel<<<GG, B>>>(batch, b3, Wlin, blin, out);
}